// round 2
// baseline (speedup 1.0000x reference)
#include <cuda_runtime.h>
#include <math.h>

#define H  1024
#define H3 3072
#define B  64
#define T  256
#define KC 64
#define JT 8

// ---------------- scratch (static __device__: no allocation at runtime) ----
static __device__ float g_GI0[(size_t)T * B * H3];  // precomputed x@W_ih0^T + b_ih0
static __device__ float g_GXF[T * B];               // x_{t+1}·u + c
static __device__ float g_u[H];
static __device__ float g_v[H];
static __device__ float g_c;
static __device__ float g_h0s[B * H];               // layer0 state
static __device__ float g_h1s[B * H];               // layer1 state
static __device__ float g_h0n[B * H];               // layer0 candidate
static __device__ float g_h1n[B * H];               // layer1 candidate
static __device__ float g_gacc[B];                  // gate dot accumulator

__device__ __forceinline__ float sigf(float x) { return 1.0f / (1.0f + expf(-x)); }

// ---------------- init: broadcast h0 into states, zero gate accum ----------
__global__ void init_kernel(const float* __restrict__ h0)
{
    int b = blockIdx.x;
    for (int j = threadIdx.x; j < H; j += blockDim.x) {
        float v = h0[j];
        g_h0s[b * H + j] = v;
        g_h1s[b * H + j] = v;
    }
    if (threadIdx.x == 0) g_gacc[b] = 0.0f;
}

// ---------------- gate folding: u = gW1^T gWF, v = gW2^T gWF, c scalar -----
__global__ void uvc_kernel(const float* __restrict__ gW1, const float* __restrict__ gW2,
                           const float* __restrict__ gWF, const float* __restrict__ gb1,
                           const float* __restrict__ gb2, const float* __restrict__ gbF)
{
    if (blockIdx.x < 2) {
        const float* W  = (blockIdx.x == 0) ? gW1 : gW2;
        float*       dst = (blockIdx.x == 0) ? g_u : g_v;
        for (int k = threadIdx.x; k < H; k += blockDim.x) {
            float s = 0.0f;
            for (int j = 0; j < H; ++j) s += gWF[j] * W[(size_t)j * H + k];
            dst[k] = s;
        }
    } else {
        __shared__ float red[256];
        float s = 0.0f;
        for (int j = threadIdx.x; j < H; j += blockDim.x) s += gWF[j] * (gb1[j] + gb2[j]);
        red[threadIdx.x] = s;
        __syncthreads();
        for (int off = 128; off > 0; off >>= 1) {
            if (threadIdx.x < off) red[threadIdx.x] += red[threadIdx.x + off];
            __syncthreads();
        }
        if (threadIdx.x == 0) g_c = red[0] + gbF[0];
    }
}

// ---------------- gate input precompute: GXF[t][b] = x[b][min(t+1,T-1)]·u + c
__global__ void gxf_kernel(const float* __restrict__ x)
{
    int t = blockIdx.x, b = blockIdx.y;
    int tn = (t + 1 < T) ? (t + 1) : (T - 1);
    const float* xr = x + ((size_t)b * T + tn) * H;
    float s = 0.0f;
    for (int k = threadIdx.x; k < H; k += blockDim.x) s += xr[k] * g_u[k];
    __shared__ float red[128];
    red[threadIdx.x] = s;
    __syncthreads();
    for (int off = 64; off > 0; off >>= 1) {
        if (threadIdx.x < off) red[threadIdx.x] += red[threadIdx.x + off];
        __syncthreads();
    }
    if (threadIdx.x == 0) g_GXF[t * B + b] = red[0] + g_c;
}

// ---------------- big precompute GEMM: GI0[t][b][3H] = x_t @ W_ih0^T + b ---
// grid (T, H/JT), 128 threads. Thread = (bg 0..15, jj 0..7), computes 4 b x 1 j x 3 gates.
__global__ void gi0_kernel(const float* __restrict__ x, const float* __restrict__ Wih0,
                           const float* __restrict__ bih0)
{
    int t  = blockIdx.x;
    int j0 = blockIdx.y * JT;
    int tid = threadIdx.x;
    int bg = tid >> 3, jj = tid & 7, b0 = bg * 4;

    __shared__ float sx[64][KC + 1];
    __shared__ float sw[24][KC + 1];

    float a0[4] = {0, 0, 0, 0}, a1[4] = {0, 0, 0, 0}, a2[4] = {0, 0, 0, 0};

    for (int kc = 0; kc < H / KC; ++kc) {
        int k0 = kc * KC;
        for (int idx = tid; idx < 64 * (KC / 4); idx += 128) {
            int r = idx >> 4, c4 = idx & 15;
            float4 v = *(const float4*)(x + ((size_t)r * T + t) * H + k0 + c4 * 4);
            sx[r][c4 * 4 + 0] = v.x; sx[r][c4 * 4 + 1] = v.y;
            sx[r][c4 * 4 + 2] = v.z; sx[r][c4 * 4 + 3] = v.w;
        }
        for (int idx = tid; idx < 24 * (KC / 4); idx += 128) {
            int wr = idx >> 4, c4 = idx & 15;
            int jl = wr / 3, g = wr - jl * 3;
            float4 v = *(const float4*)(Wih0 + (size_t)(g * H + j0 + jl) * H + k0 + c4 * 4);
            sw[wr][c4 * 4 + 0] = v.x; sw[wr][c4 * 4 + 1] = v.y;
            sw[wr][c4 * 4 + 2] = v.z; sw[wr][c4 * 4 + 3] = v.w;
        }
        __syncthreads();
        #pragma unroll 8
        for (int k = 0; k < KC; ++k) {
            float w0 = sw[jj * 3 + 0][k], w1 = sw[jj * 3 + 1][k], w2 = sw[jj * 3 + 2][k];
            #pragma unroll
            for (int i = 0; i < 4; ++i) {
                float xv = sx[b0 + i][k];
                a0[i] += xv * w0; a1[i] += xv * w1; a2[i] += xv * w2;
            }
        }
        __syncthreads();
    }
    int j = j0 + jj;
    float br = bih0[j], bz = bih0[H + j], bn = bih0[2 * H + j];
    #pragma unroll
    for (int i = 0; i < 4; ++i) {
        int b = b0 + i;
        size_t base = ((size_t)t * B + b) * H3;
        g_GI0[base + j]         = a0[i] + br;
        g_GI0[base + H + j]     = a1[i] + bz;
        g_GI0[base + 2 * H + j] = a2[i] + bn;
    }
}

// ---------------- layer0 step: h0n = GRUcell(GI0[t], h0s; W_hh0) -----------
__global__ void layer0_kernel(int t, const float* __restrict__ Whh0,
                              const float* __restrict__ bhh0)
{
    int j0 = blockIdx.x * JT;
    int tid = threadIdx.x;
    int bg = tid >> 3, jj = tid & 7, b0 = bg * 4;

    __shared__ float sh[64][KC + 1];
    __shared__ float sw[24][KC + 1];

    float a0[4] = {0, 0, 0, 0}, a1[4] = {0, 0, 0, 0}, a2[4] = {0, 0, 0, 0};

    for (int kc = 0; kc < H / KC; ++kc) {
        int k0 = kc * KC;
        for (int idx = tid; idx < 64 * (KC / 4); idx += 128) {
            int r = idx >> 4, c4 = idx & 15;
            float4 v = *(const float4*)(g_h0s + (size_t)r * H + k0 + c4 * 4);
            sh[r][c4 * 4 + 0] = v.x; sh[r][c4 * 4 + 1] = v.y;
            sh[r][c4 * 4 + 2] = v.z; sh[r][c4 * 4 + 3] = v.w;
        }
        for (int idx = tid; idx < 24 * (KC / 4); idx += 128) {
            int wr = idx >> 4, c4 = idx & 15;
            int jl = wr / 3, g = wr - jl * 3;
            float4 v = *(const float4*)(Whh0 + (size_t)(g * H + j0 + jl) * H + k0 + c4 * 4);
            sw[wr][c4 * 4 + 0] = v.x; sw[wr][c4 * 4 + 1] = v.y;
            sw[wr][c4 * 4 + 2] = v.z; sw[wr][c4 * 4 + 3] = v.w;
        }
        __syncthreads();
        #pragma unroll 8
        for (int k = 0; k < KC; ++k) {
            float w0 = sw[jj * 3 + 0][k], w1 = sw[jj * 3 + 1][k], w2 = sw[jj * 3 + 2][k];
            #pragma unroll
            for (int i = 0; i < 4; ++i) {
                float hv = sh[b0 + i][k];
                a0[i] += hv * w0; a1[i] += hv * w1; a2[i] += hv * w2;
            }
        }
        __syncthreads();
    }
    int j = j0 + jj;
    float br = bhh0[j], bz = bhh0[H + j], bn = bhh0[2 * H + j];
    #pragma unroll
    for (int i = 0; i < 4; ++i) {
        int b = b0 + i;
        const float* gi = g_GI0 + ((size_t)t * B + b) * H3;
        float r = sigf(gi[j] + a0[i] + br);
        float z = sigf(gi[H + j] + a1[i] + bz);
        float n = tanhf(gi[2 * H + j] + r * (a2[i] + bn));
        float hp = g_h0s[b * H + j];
        g_h0n[b * H + j] = (1.0f - z) * n + z * hp;
    }
}

// ---------------- layer1 step: h1n = GRUcell(h0n@Wih1+b, h1s; W_hh1) + gate dot
__global__ void layer1_kernel(const float* __restrict__ Wih1, const float* __restrict__ Whh1,
                              const float* __restrict__ bih1, const float* __restrict__ bhh1)
{
    int j0 = blockIdx.x * JT;
    int tid = threadIdx.x;
    int bg = tid >> 3, jj = tid & 7, b0 = bg * 4;

    __shared__ float sx[64][KC + 1];   // layer0 output (this step's input)
    __shared__ float sh[64][KC + 1];   // layer1 previous state
    __shared__ float sw[48][KC + 1];   // 0..23: W_ih1 rows, 24..47: W_hh1 rows

    float ai0[4] = {0, 0, 0, 0}, ai1[4] = {0, 0, 0, 0}, ai2[4] = {0, 0, 0, 0};
    float ah0[4] = {0, 0, 0, 0}, ah1[4] = {0, 0, 0, 0}, ah2[4] = {0, 0, 0, 0};

    for (int kc = 0; kc < H / KC; ++kc) {
        int k0 = kc * KC;
        for (int idx = tid; idx < 64 * (KC / 4); idx += 128) {
            int r = idx >> 4, c4 = idx & 15;
            float4 v = *(const float4*)(g_h0n + (size_t)r * H + k0 + c4 * 4);
            sx[r][c4 * 4 + 0] = v.x; sx[r][c4 * 4 + 1] = v.y;
            sx[r][c4 * 4 + 2] = v.z; sx[r][c4 * 4 + 3] = v.w;
            float4 u = *(const float4*)(g_h1s + (size_t)r * H + k0 + c4 * 4);
            sh[r][c4 * 4 + 0] = u.x; sh[r][c4 * 4 + 1] = u.y;
            sh[r][c4 * 4 + 2] = u.z; sh[r][c4 * 4 + 3] = u.w;
        }
        for (int idx = tid; idx < 48 * (KC / 4); idx += 128) {
            int wr = idx >> 4, c4 = idx & 15;
            int wl = (wr < 24) ? wr : (wr - 24);
            int jl = wl / 3, g = wl - jl * 3;
            const float* src = (wr < 24) ? Wih1 : Whh1;
            float4 v = *(const float4*)(src + (size_t)(g * H + j0 + jl) * H + k0 + c4 * 4);
            sw[wr][c4 * 4 + 0] = v.x; sw[wr][c4 * 4 + 1] = v.y;
            sw[wr][c4 * 4 + 2] = v.z; sw[wr][c4 * 4 + 3] = v.w;
        }
        __syncthreads();
        #pragma unroll 4
        for (int k = 0; k < KC; ++k) {
            float wi0 = sw[jj * 3 + 0][k], wi1 = sw[jj * 3 + 1][k], wi2 = sw[jj * 3 + 2][k];
            float wh0 = sw[24 + jj * 3 + 0][k], wh1 = sw[24 + jj * 3 + 1][k], wh2 = sw[24 + jj * 3 + 2][k];
            #pragma unroll
            for (int i = 0; i < 4; ++i) {
                float xv = sx[b0 + i][k];
                float hv = sh[b0 + i][k];
                ai0[i] += xv * wi0; ai1[i] += xv * wi1; ai2[i] += xv * wi2;
                ah0[i] += hv * wh0; ah1[i] += hv * wh1; ah2[i] += hv * wh2;
            }
        }
        __syncthreads();
    }
    int j = j0 + jj;
    float bir = bih1[j], biz = bih1[H + j], bin = bih1[2 * H + j];
    float bhr = bhh1[j], bhz = bhh1[H + j], bhn = bhh1[2 * H + j];
    float vj = g_v[j];
    float gp[4];
    #pragma unroll
    for (int i = 0; i < 4; ++i) {
        int b = b0 + i;
        float r = sigf(ai0[i] + bir + ah0[i] + bhr);
        float z = sigf(ai1[i] + biz + ah1[i] + bhz);
        float n = tanhf(ai2[i] + bin + r * (ah2[i] + bhn));
        float hp = g_h1s[b * H + j];
        float hn = (1.0f - z) * n + z * hp;
        g_h1n[b * H + j] = hn;
        gp[i] = hn * vj;
    }
    // reduce gate partials across the 8 jj lanes sharing this (bg) group
    #pragma unroll
    for (int s = 1; s < 8; s <<= 1) {
        #pragma unroll
        for (int i = 0; i < 4; ++i) gp[i] += __shfl_down_sync(0xffffffffu, gp[i], s);
    }
    if ((tid & 7) == 0) {
        #pragma unroll
        for (int i = 0; i < 4; ++i) atomicAdd(&g_gacc[b0 + i], gp[i]);
    }
}

// ---------------- gate + state update + output write -----------------------
__global__ void update_kernel(int t, const int* __restrict__ lengths,
                              const float* __restrict__ h0, float* __restrict__ out)
{
    int b = blockIdx.x;
    __shared__ int s_valid, s_reset;
    if (threadIdx.x == 0) {
        float a = g_GXF[t * B + b] + g_gacc[b];
        g_gacc[b] = 0.0f;
        float graw = sigf(a);
        int len = lengths[b];
        float gt = (t == len - 1) ? 1.0f : graw;
        int valid = (t < len);
        out[(size_t)B * T * H + (size_t)b * T + t] = valid ? gt : 0.0f;
        s_valid = valid;
        s_reset = (gt > 0.5f) && valid;
    }
    __syncthreads();
    int valid = s_valid, reset = s_reset;
    float* orow = out + ((size_t)b * T + t) * H;
    for (int j = threadIdx.x; j < H; j += blockDim.x) {
        float h1n = g_h1n[b * H + j];
        orow[j] = valid ? h1n : 0.0f;
        if (valid) {
            float hi = h0[j];
            g_h0s[b * H + j] = reset ? hi : g_h0n[b * H + j];
            g_h1s[b * H + j] = reset ? hi : h1n;
        }
    }
}

// ---------------- host ------------------------------------------------------
extern "C" void kernel_launch(void* const* d_in, const int* in_sizes, int n_in,
                              void* d_out, int out_size)
{
    (void)in_sizes; (void)n_in; (void)out_size;
    const float* x       = (const float*)d_in[0];
    const float* h0      = (const float*)d_in[1];
    const int*   lengths = (const int*)d_in[2];
    const float* W_ih    = (const float*)d_in[3];
    const float* W_hh    = (const float*)d_in[4];
    const float* b_ih    = (const float*)d_in[5];
    const float* b_hh    = (const float*)d_in[6];
    const float* gW1     = (const float*)d_in[7];
    const float* gb1     = (const float*)d_in[8];
    const float* gW2     = (const float*)d_in[9];
    const float* gb2     = (const float*)d_in[10];
    const float* gWF     = (const float*)d_in[11];
    const float* gbF     = (const float*)d_in[12];
    float* out = (float*)d_out;

    const float* Wih0 = W_ih;
    const float* Wih1 = W_ih + (size_t)H3 * H;
    const float* Whh0 = W_hh;
    const float* Whh1 = W_hh + (size_t)H3 * H;
    const float* bih0 = b_ih;
    const float* bih1 = b_ih + H3;
    const float* bhh0 = b_hh;
    const float* bhh1 = b_hh + H3;

    init_kernel<<<B, 256>>>(h0);
    uvc_kernel<<<3, 256>>>(gW1, gW2, gWF, gb1, gb2, gbF);
    gi0_kernel<<<dim3(T, H / JT), 128>>>(x, Wih0, bih0);
    gxf_kernel<<<dim3(T, B), 128>>>(x);

    for (int t = 0; t < T; ++t) {
        layer0_kernel<<<H / JT, 128>>>(t, Whh0, bhh0);
        layer1_kernel<<<H / JT, 128>>>(Wih1, Whh1, bih1, bhh1);
        update_kernel<<<B, 256>>>(t, lengths, h0, out);
    }
}